// round 6
// baseline (speedup 1.0000x reference)
#include <cuda_runtime.h>
#include <cuda_bf16.h>
#include <cstdint>

// ============================================================
// Attention1D: LN -> QKV GEMM -> 8-head window attention -> out GEMM
// Generic-PTX mma.sync tf32 path (harness PTX stage = compute_103, no 'a',
// so tcgen05 is unavailable). All operands stored in FRAGMENT-NATIVE order:
//   A: [ks][m_tile][lane]{a0,a1,a2,a3}   (one LDS.128 per tile per ks)
//   B: [ks][n_tile][lane]{b0,b1}         (one LDS.64  per tile per ks)
// so staging is a raw linear copy and smem loads are conflict-free.
// ============================================================

#define FULLM 0xffffffffu

// weight scratch (tf32-rounded, fragment order)
__device__ __align__(16) float g_w1t[8 * 32 * 2 * 6 * 32 * 2];  // [h][ks][ng][nt][lane][2]
__device__ __align__(16) float g_w2t[32 * 32 * 32 * 2];         // [ks][nt][lane][2]
// attention output scratch, fragment order [cta][ks2(32)][mt2(8)][lane(32)][j2(4)]
__device__ float g_a2[67108864];

static __device__ __forceinline__ float f2tf(float f) {
    uint32_t o; asm("cvt.rna.tf32.f32 %0, %1;" : "=r"(o) : "f"(f));
    return __uint_as_float(o);
}
static __device__ __forceinline__ void mma8(float* c, const float4& a, const float2& b) {
    asm volatile(
        "mma.sync.aligned.m16n8k8.row.col.f32.tf32.tf32.f32 "
        "{%0,%1,%2,%3}, {%4,%5,%6,%7}, {%8,%9}, {%0,%1,%2,%3};"
        : "+f"(c[0]), "+f"(c[1]), "+f"(c[2]), "+f"(c[3])
        : "r"(__float_as_uint(a.x)), "r"(__float_as_uint(a.y)),
          "r"(__float_as_uint(a.z)), "r"(__float_as_uint(a.w)),
          "r"(__float_as_uint(b.x)), "r"(__float_as_uint(b.y)));
}
static __device__ __forceinline__ uint32_t smem_u32(const void* p) {
    uint32_t a;
    asm("{ .reg .u64 t; cvta.to.shared.u64 t, %1; cvt.u32.u64 %0, t; }" : "=r"(a) : "l"(p));
    return a;
}
#define CP16(dst, src) \
    asm volatile("cp.async.ca.shared.global [%0], [%1], 16;" :: "r"(dst), "l"(src))
#define CP_COMMIT() asm volatile("cp.async.commit_group;" ::: "memory")
#define CP_WAIT(n)  asm volatile("cp.async.wait_group %0;" :: "n"(n) : "memory")

// ---------------- weight prep (tf32 round + fragment-order transpose) ----------------
__global__ void prep_w1(const float* __restrict__ wqkv) {
    int o = blockIdx.x * 256 + threadIdx.x;          // < 196608
    int pair = o & 1;
    int lane = (o >> 1) & 31;
    int r2 = o >> 6;
    int nt = r2 % 6;
    int r3 = r2 / 6;
    int ng = r3 & 1;
    int r4 = r3 >> 1;
    int ks = r4 & 31;
    int h  = r4 >> 5;
    int t = lane & 3, g = lane >> 2;
    int kg = ks * 8 + t + pair * 4;                  // K index (0..255)
    int s  = nt >> 1;                                // 0=q,1=k,2=v
    int d  = ng * 16 + (nt & 1) * 8 + g;             // dim within head
    g_w1t[o] = f2tf(wqkv[kg * 768 + s * 256 + h * 32 + d]);
}
__global__ void prep_w2(const float* __restrict__ wout) {
    int o = blockIdx.x * 256 + threadIdx.x;          // < 65536
    int pair = o & 1;
    int lane = (o >> 1) & 31;
    int nt = (o >> 6) & 31;
    int ks = o >> 11;
    int t = lane & 3, g = lane >> 2;
    int kg = ks * 8 + t + pair * 4;
    int n  = nt * 8 + g;
    g_w2t[o] = f2tf(wout[kg * 256 + n]);
}

// ============================================================
// K1: LN + QKV GEMM + attention -> g_a2
// warps: mg = wid&3 (rows 32mg..+31), ng = wid>>2 (dim-half of q/k/v)
// smem: A-frag 128KB | B ring 3x24KB | sim-exchange 8KB
// ============================================================
#define K1_SXA   32768
#define K1_RING  18432
#define K1_EXCH  2048
#define K1_SMEM  ((K1_SXA + K1_RING + K1_EXCH) * 4)

__global__ void __launch_bounds__(256, 1) attn_k1(
    const float* __restrict__ x, const float* __restrict__ lnw,
    const float* __restrict__ lnb, const float* __restrict__ relt)
{
    extern __shared__ __align__(16) float sm[];
    float* const sxA   = sm;
    float* const srng  = sm + K1_SXA;
    float* const sexch = sm + K1_SXA + K1_RING;
    const int tid  = threadIdx.x;
    const int wid  = tid >> 5;
    const int lane = tid & 31;
    const int g = lane >> 2, t = lane & 3;
    const int mg = wid & 3, ng = wid >> 2;
    const int cta = blockIdx.x;
    const uint32_t srng_u = smem_u32(srng);

    // stage chunk cid (6144 floats, linear) into ring slot cid%3
    auto stage = [&](int cid) {
        uint32_t dst = srng_u + (uint32_t)(cid % 3) * 24576u + (uint32_t)tid * 16u;
        const float* src = g_w1t + cid * 6144 + tid * 4;
        #pragma unroll
        for (int i = 0; i < 6; ++i) CP16(dst + i * 4096u, src + i * 1024);
        CP_COMMIT();
    };
    stage(0);
    stage(1);

    // ---- LayerNorm -> fragment-order tf32 A (overlaps cp.async) ----
    {
        const float* xr = x + (size_t)cta * 128 * 256;
        const float4 w0 = *(const float4*)(lnw + lane * 4);
        const float4 w1 = *(const float4*)(lnw + 128 + lane * 4);
        const float4 b0 = *(const float4*)(lnb + lane * 4);
        const float4 b1 = *(const float4*)(lnb + 128 + lane * 4);
        #pragma unroll 2
        for (int rr = 0; rr < 16; ++rr) {
            const int r = wid * 16 + rr;
            const float4 xa = *(const float4*)(xr + r * 256 + lane * 4);
            const float4 xb = *(const float4*)(xr + r * 256 + 128 + lane * 4);
            float s  = xa.x + xa.y + xa.z + xa.w + xb.x + xb.y + xb.z + xb.w;
            float ss = xa.x*xa.x + xa.y*xa.y + xa.z*xa.z + xa.w*xa.w
                     + xb.x*xb.x + xb.y*xb.y + xb.z*xb.z + xb.w*xb.w;
            #pragma unroll
            for (int o2 = 16; o2; o2 >>= 1) {
                s  += __shfl_xor_sync(FULLM, s,  o2);
                ss += __shfl_xor_sync(FULLM, ss, o2);
            }
            const float mu   = s * (1.0f / 256.0f);
            const float rstd = rsqrtf(ss * (1.0f / 256.0f) - mu * mu + 1e-5f);
            float vals[8];
            vals[0] = f2tf((xa.x - mu) * rstd * w0.x + b0.x);
            vals[1] = f2tf((xa.y - mu) * rstd * w0.y + b0.y);
            vals[2] = f2tf((xa.z - mu) * rstd * w0.z + b0.z);
            vals[3] = f2tf((xa.w - mu) * rstd * w0.w + b0.w);
            vals[4] = f2tf((xb.x - mu) * rstd * w1.x + b1.x);
            vals[5] = f2tf((xb.y - mu) * rstd * w1.y + b1.y);
            vals[6] = f2tf((xb.z - mu) * rstd * w1.z + b1.z);
            vals[7] = f2tf((xb.w - mu) * rstd * w1.w + b1.w);
            const int mt = r >> 4, rl = r & 15;
            const int jb = rl >> 3, g2 = rl & 7;
            #pragma unroll
            for (int cc = 0; cc < 4; ++cc) {
                {   const int c = lane * 4 + cc;
                    sxA[((c >> 3) * 8 + mt) * 128 + (g2 * 4 + (c & 3)) * 4 + jb + ((c & 4) >> 1)] = vals[cc]; }
                {   const int c = 128 + lane * 4 + cc;
                    sxA[((c >> 3) * 8 + mt) * 128 + (g2 * 4 + (c & 3)) * 4 + jb + ((c & 4) >> 1)] = vals[4 + cc]; }
            }
        }
    }

    float acc[6][2][4];
    #pragma unroll
    for (int n = 0; n < 6; ++n)
        #pragma unroll
        for (int m = 0; m < 2; ++m)
            #pragma unroll
            for (int e = 0; e < 4; ++e) acc[n][m][e] = 0.0f;

    const float scale = 0.17677669529663689f;        // 32^-0.5
    float bias[8];
    const float4* const sa4 = (const float4*)sxA;

    #pragma unroll 1
    for (int cid = 0; cid < 32; ++cid) {
        const int h = cid >> 2, q = cid & 3;
        if (cid == 31) { CP_WAIT(0); } else { CP_WAIT(1); }
        __syncthreads();                              // chunk cid ready; slot (cid+2)%3 free
        if (cid + 2 < 32) stage(cid + 2);

        if (q == 0) {
            #pragma unroll
            for (int j = 0; j < 8; ++j) {
                int ridx = (g >= 1 && j >= 1) ? (g - j + 6) : 13;
                bias[j] = __ldg(relt + ridx * 8 + h);
            }
        }

        // ---- GEMM1 on chunk: K=64, warp tile m32 x n48 ----
        const float2* const bw2 = (const float2*)(srng + (cid % 3) * 6144);
        #pragma unroll
        for (int ks = 0; ks < 8; ++ks) {
            const float4 fa0 = sa4[((q * 8 + ks) * 8 + mg * 2 + 0) * 32 + lane];
            const float4 fa1 = sa4[((q * 8 + ks) * 8 + mg * 2 + 1) * 32 + lane];
            #pragma unroll
            for (int nt = 0; nt < 6; ++nt) {
                const float2 fb = bw2[((ks * 2 + ng) * 6 + nt) * 32 + lane];
                mma8(acc[nt][0], fa0, fb);
                mma8(acc[nt][1], fa1, fb);
            }
        }

        if (q == 3) {
            // ================= attention for head h =================
            // warp holds, for rows [32mg,32mg+32), dims [16ng,16ng+16) of q,k,v.
            // block blk=(mt,hi): one batch of 8 slots (rows mt*16+hi*8+g).
            float p[4][8];
            float vvv[4][4];
            // phase 1: partial sims over this warp's 16 dims
            #pragma unroll
            for (int blk = 0; blk < 4; ++blk) {
                const int mt = blk >> 1, e0 = (blk & 1) * 2;
                float qv[4] = {acc[0][mt][e0], acc[0][mt][e0 + 1], acc[1][mt][e0], acc[1][mt][e0 + 1]};
                float kv[4] = {acc[2][mt][e0], acc[2][mt][e0 + 1], acc[3][mt][e0], acc[3][mt][e0 + 1]};
                vvv[blk][0] = acc[4][mt][e0]; vvv[blk][1] = acc[4][mt][e0 + 1];
                vvv[blk][2] = acc[5][mt][e0]; vvv[blk][3] = acc[5][mt][e0 + 1];
                #pragma unroll
                for (int j = 0; j < 8; ++j) {
                    float s = 0.0f;
                    #pragma unroll
                    for (int r = 0; r < 4; ++r)
                        s = fmaf(qv[r], __shfl_sync(FULLM, kv[r], j * 4 + t), s);
                    s += __shfl_xor_sync(FULLM, s, 1);
                    s += __shfl_xor_sync(FULLM, s, 2);
                    p[blk][j] = s;
                }
                if (t == 0) {
                    float* e = sexch + ((mg * 2 + ng) * 4 + blk) * 64 + g * 8;
                    *(float4*)(e)     = make_float4(p[blk][0], p[blk][1], p[blk][2], p[blk][3]);
                    *(float4*)(e + 4) = make_float4(p[blk][4], p[blk][5], p[blk][6], p[blk][7]);
                }
            }
            __syncthreads();
            // phase 2: merge halves, softmax, attn@v, write to a2 bounce buffer
            float* const a2buf = srng + (cid % 3) * 6144;   // freed ring slot (24KB >= 16KB)
            #pragma unroll
            for (int blk = 0; blk < 4; ++blk) {
                const int mt = blk >> 1, hi = blk & 1;
                const float* oth = sexch + ((mg * 2 + (1 - ng)) * 4 + blk) * 64 + g * 8;
                const float4 o0 = *(const float4*)(oth);
                const float4 o1 = *(const float4*)(oth + 4);
                float simv[8];
                simv[0] = (p[blk][0] + o0.x) * scale + bias[0];
                simv[1] = (p[blk][1] + o0.y) * scale + bias[1];
                simv[2] = (p[blk][2] + o0.z) * scale + bias[2];
                simv[3] = (p[blk][3] + o0.w) * scale + bias[3];
                simv[4] = (p[blk][4] + o1.x) * scale + bias[4];
                simv[5] = (p[blk][5] + o1.y) * scale + bias[5];
                simv[6] = (p[blk][6] + o1.z) * scale + bias[6];
                simv[7] = (p[blk][7] + o1.w) * scale + bias[7];
                float mx = simv[0];
                #pragma unroll
                for (int j = 1; j < 8; ++j) mx = fmaxf(mx, simv[j]);
                float ssum = 0.0f;
                #pragma unroll
                for (int j = 0; j < 8; ++j) { simv[j] = __expf(simv[j] - mx); ssum += simv[j]; }
                const float inv = 1.0f / ssum;
                float ov[4] = {0.0f, 0.0f, 0.0f, 0.0f};
                #pragma unroll
                for (int j = 0; j < 8; ++j) {
                    const float aj = simv[j] * inv;
                    #pragma unroll
                    for (int r = 0; r < 4; ++r)
                        ov[r] = fmaf(aj, __shfl_sync(FULLM, vvv[blk][r], j * 4 + t), ov[r]);
                }
                // scatter into bounce buffer, fragment order [ks2l(4)][mt2(8)][lane(32)][j2(4)]
                const int mt2 = mg * 2 + mt;
                const int khi2 = t >> 1;
                const int j2 = hi + 2 * khi2;
                #pragma unroll
                for (int r2 = 0; r2 < 4; ++r2) {
                    const int nn = r2 >> 1, e = r2 & 1;
                    const int ks2l = ng * 2 + nn;
                    const int t2 = (2 * t + e) & 3;
                    a2buf[((ks2l * 8 + mt2) * 32 + g * 4 + t2) * 4 + j2] = f2tf(ov[r2]);
                }
                #pragma unroll
                for (int n = 0; n < 6; ++n) {
                    acc[n][mt][2 * hi] = 0.0f;
                    acc[n][mt][2 * hi + 1] = 0.0f;
                }
            }
            __syncthreads();
            // coalesced copy: bounce buffer (4096 floats) -> g_a2 head block
            {
                float* dst = g_a2 + (size_t)cta * 32768 + h * 4096;
                #pragma unroll
                for (int i = 0; i < 4; ++i) {
                    const int fi = (tid + i * 256) * 4;
                    *(float4*)(dst + fi) = *(const float4*)(a2buf + fi);
                }
            }
        }
    }
}

// ============================================================
// K2: out = A2 @ w_out   (K=256 in 8 chunks of 32, ring-3)
// warps: mgrp = wid&1 (rows 64*mgrp, m-tiles 4), ngrp = wid>>1 (8 n-tiles)
// smem: ring 3 x (A 16KB + B 32KB) = 144KB; epilogue reuses for transpose
// ============================================================
#define K2_SLOT  12288
#define K2_SMEM  (3 * K2_SLOT * 4)

__global__ void __launch_bounds__(256, 1) attn_k2(float* __restrict__ out)
{
    extern __shared__ __align__(16) float sm[];
    const int tid  = threadIdx.x;
    const int wid  = tid >> 5;
    const int lane = tid & 31;
    const int g = lane >> 2, t = lane & 3;
    const int mgrp = wid & 1, ngrp = wid >> 1;
    const int cta = blockIdx.x;
    const uint32_t sm_u = smem_u32(sm);

    auto stage = [&](int q) {
        const uint32_t dstb = sm_u + (uint32_t)(q % 3) * (K2_SLOT * 4u);
        const float* asrc = g_a2 + (size_t)cta * 32768 + q * 4096;
        #pragma unroll
        for (int i = 0; i < 4; ++i)
            CP16(dstb + (uint32_t)(tid + i * 256) * 16u, asrc + (tid + i * 256) * 4);
        const float* bsrc = g_w2t + q * 8192;
        #pragma unroll
        for (int i = 0; i < 8; ++i)
            CP16(dstb + 16384u + (uint32_t)(tid + i * 256) * 16u, bsrc + (tid + i * 256) * 4);
        CP_COMMIT();
    };
    stage(0);
    stage(1);

    float acc[8][4][4];
    #pragma unroll
    for (int n = 0; n < 8; ++n)
        #pragma unroll
        for (int m = 0; m < 4; ++m)
            #pragma unroll
            for (int e = 0; e < 4; ++e) acc[n][m][e] = 0.0f;

    #pragma unroll 1
    for (int q = 0; q < 8; ++q) {
        if (q == 7) { CP_WAIT(0); } else { CP_WAIT(1); }
        __syncthreads();
        if (q + 2 < 8) stage(q + 2);
        const float4* const ab4 = (const float4*)(sm + (q % 3) * K2_SLOT);
        const float2* const bb2 = (const float2*)(sm + (q % 3) * K2_SLOT + 4096);
        #pragma unroll
        for (int ksl = 0; ksl < 4; ++ksl) {
            float4 fa[4];
            #pragma unroll
            for (int m = 0; m < 4; ++m)
                fa[m] = ab4[((ksl * 8 + mgrp * 4 + m) * 32) + lane];
            #pragma unroll
            for (int ntl = 0; ntl < 8; ++ntl) {
                const float2 fb = bb2[(ksl * 32 + ngrp * 8 + ntl) * 32 + lane];
                #pragma unroll
                for (int m = 0; m < 4; ++m) mma8(acc[ntl][m], fa[m], fb);
            }
        }
    }

    // epilogue: regs -> padded smem -> coalesced STG.128
    __syncthreads();
    #pragma unroll
    for (int ntl = 0; ntl < 8; ++ntl) {
        #pragma unroll
        for (int m = 0; m < 4; ++m) {
            const int row0 = mgrp * 64 + m * 16 + g;
            const int col  = (ngrp * 8 + ntl) * 8 + 2 * t;
            *(float2*)&sm[row0 * 260 + col]       = make_float2(acc[ntl][m][0], acc[ntl][m][1]);
            *(float2*)&sm[(row0 + 8) * 260 + col] = make_float2(acc[ntl][m][2], acc[ntl][m][3]);
        }
    }
    __syncthreads();
    float* const od = out + (size_t)cta * 32768;
    #pragma unroll
    for (int i = 0; i < 32; ++i) {
        const int idx = tid + i * 256;
        const int r = idx >> 6, c4 = idx & 63;
        *(float4*)(od + r * 256 + c4 * 4) = *(const float4*)&sm[r * 260 + c4 * 4];
    }
}

extern "C" void kernel_launch(void* const* d_in, const int* in_sizes, int n_in,
                              void* d_out, int out_size) {
    const float* x    = (const float*)d_in[0];
    const float* lnw  = (const float*)d_in[1];
    const float* lnb  = (const float*)d_in[2];
    const float* wqkv = (const float*)d_in[3];
    const float* wout = (const float*)d_in[4];
    const float* relt = (const float*)d_in[5];
    // d_in[6] (rel_pos_indices) recomputed analytically in-kernel.

    prep_w1<<<768, 256>>>(wqkv);
    prep_w2<<<256, 256>>>(wout);

    cudaFuncSetAttribute(attn_k1, cudaFuncAttributeMaxDynamicSharedMemorySize, K1_SMEM);
    cudaFuncSetAttribute(attn_k2, cudaFuncAttributeMaxDynamicSharedMemorySize, K2_SMEM);
    attn_k1<<<2048, 256, K1_SMEM>>>(x, lnw, lnb, relt);
    attn_k2<<<2048, 256, K2_SMEM>>>((float*)d_out);
}

// round 7
// speedup vs baseline: 1.0366x; 1.0366x over previous
#include <cuda_runtime.h>
#include <cuda_bf16.h>
#include <cstdint>

// ============================================================
// Attention1D: LN -> QKV GEMM -> 8-head window attention -> out GEMM
// mma.sync tf32 path (tcgen05 unavailable: harness PTX targets compute_103).
// K1: xn row-major XOR-swizzled (conflict-free), B1 fragment-native.
// K2: 512 threads, warp m32 x n64, no spills.
// ============================================================

#define FULLM 0xffffffffu

// B1 fragment order: [cid(32)=h*4+q][ks(8)][nt(12)][lane(32)][pair(2)]
__device__ __align__(16) float g_w1t[32 * 8 * 12 * 64];
// B2 fragment order: [q(8)][ksl(4)][nt(32)][lane(32)][pair(2)]
__device__ __align__(16) float g_w2t[8 * 4 * 32 * 64];
// A2 scratch: [cta][head(8)][row(128)][col(32) xor-swizzled], 268 MB
__device__ float g_a2[67108864];

static __device__ __forceinline__ float f2tf(float f) {
    uint32_t o; asm("cvt.rna.tf32.f32 %0, %1;" : "=r"(o) : "f"(f));
    return __uint_as_float(o);
}
static __device__ __forceinline__ void mma8(float* c, const float4& a, const float2& b) {
    asm volatile(
        "mma.sync.aligned.m16n8k8.row.col.f32.tf32.tf32.f32 "
        "{%0,%1,%2,%3}, {%4,%5,%6,%7}, {%8,%9}, {%0,%1,%2,%3};"
        : "+f"(c[0]), "+f"(c[1]), "+f"(c[2]), "+f"(c[3])
        : "r"(__float_as_uint(a.x)), "r"(__float_as_uint(a.y)),
          "r"(__float_as_uint(a.z)), "r"(__float_as_uint(a.w)),
          "r"(__float_as_uint(b.x)), "r"(__float_as_uint(b.y)));
}
static __device__ __forceinline__ uint32_t smem_u32(const void* p) {
    uint32_t a;
    asm("{ .reg .u64 t; cvta.to.shared.u64 t, %1; cvt.u32.u64 %0, t; }" : "=r"(a) : "l"(p));
    return a;
}
#define CP16(dst, src) \
    asm volatile("cp.async.ca.shared.global [%0], [%1], 16;" :: "r"(dst), "l"(src))
#define CP_COMMIT() asm volatile("cp.async.commit_group;" ::: "memory")
#define CP_WAIT(n)  asm volatile("cp.async.wait_group %0;" :: "n"(n) : "memory")

// ---------------- weight prep (tf32 round + fragment-order transpose) ----------------
__global__ void prep_w1(const float* __restrict__ wqkv) {
    int o = blockIdx.x * 256 + threadIdx.x;          // < 196608
    int pair = o & 1;
    int lane = (o >> 1) & 31;
    int u = o >> 6;                                  // 0..3071
    int nt = u % 12;
    int v = u / 12;
    int ksl = v & 7;
    int cid = v >> 3;                                // 0..31
    int h = cid >> 2, q = cid & 3;
    int t = lane & 3, g = lane >> 2;
    int k = q * 64 + ksl * 8 + t + pair * 4;         // 0..255
    int s = nt >> 2;                                 // 0=q,1=k,2=v
    int d = (nt & 3) * 8 + g;                        // dim within head
    g_w1t[o] = f2tf(wqkv[k * 768 + s * 256 + h * 32 + d]);
}
__global__ void prep_w2(const float* __restrict__ wout) {
    int o = blockIdx.x * 256 + threadIdx.x;          // < 65536
    int pair = o & 1;
    int lane = (o >> 1) & 31;
    int nt = (o >> 6) & 31;
    int ksl = (o >> 11) & 3;
    int q = o >> 13;
    int t = lane & 3, g = lane >> 2;
    int k = q * 32 + ksl * 8 + t + pair * 4;
    int n = nt * 8 + g;
    g_w2t[o] = f2tf(wout[k * 256 + n]);
}

// ============================================================
// K1: LN + QKV GEMM + attention -> g_a2
// 8 warps, warp = m16 (rows wid*16..+15) x n96 (q|k|v of head h).
// smem: xn 128KB (row-major xor-swizzled) + B1 ring 3x24KB
// ============================================================
#define K1_SMEM ((32768 + 3 * 6144) * 4)

__global__ void __launch_bounds__(256, 1) attn_k1(
    const float* __restrict__ x, const float* __restrict__ lnw,
    const float* __restrict__ lnb, const float* __restrict__ relt)
{
    extern __shared__ __align__(16) float sm[];
    float* const sxn  = sm;              // 32768 floats
    float* const srng = sm + 32768;      // 3 * 6144 floats
    const int tid  = threadIdx.x;
    const int wid  = tid >> 5;
    const int lane = tid & 31;
    const int g = lane >> 2, t = lane & 3;
    const int cta = blockIdx.x;
    const uint32_t srng_u = smem_u32(srng);

    // stage chunk cid (6144 floats, linear) into ring slot cid%3
    auto stage = [&](int cid2) {
        uint32_t dst = srng_u + (uint32_t)(cid2 % 3) * 24576u + (uint32_t)tid * 16u;
        const float* src = g_w1t + cid2 * 6144 + tid * 4;
        #pragma unroll
        for (int i = 0; i < 6; ++i) CP16(dst + i * 4096u, src + i * 1024);
        CP_COMMIT();
    };
    stage(0);
    stage(1);

    // ---- LayerNorm -> xor-swizzled row-major tf32 xn (overlaps cp.async) ----
    {
        const float* xr = x + (size_t)cta * 128 * 256;
        const float4 w0 = *(const float4*)(lnw + lane * 4);
        const float4 w1 = *(const float4*)(lnw + 128 + lane * 4);
        const float4 b0 = *(const float4*)(lnb + lane * 4);
        const float4 b1 = *(const float4*)(lnb + 128 + lane * 4);
        #pragma unroll 2
        for (int rr = 0; rr < 16; ++rr) {
            const int r = wid * 16 + rr;
            const float4 xa = *(const float4*)(xr + r * 256 + lane * 4);
            const float4 xb = *(const float4*)(xr + r * 256 + 128 + lane * 4);
            float s  = xa.x + xa.y + xa.z + xa.w + xb.x + xb.y + xb.z + xb.w;
            float ss = xa.x*xa.x + xa.y*xa.y + xa.z*xa.z + xa.w*xa.w
                     + xb.x*xb.x + xb.y*xb.y + xb.z*xb.z + xb.w*xb.w;
            #pragma unroll
            for (int o2 = 16; o2; o2 >>= 1) {
                s  += __shfl_xor_sync(FULLM, s,  o2);
                ss += __shfl_xor_sync(FULLM, ss, o2);
            }
            const float mu   = s * (1.0f / 256.0f);
            const float rstd = rsqrtf(ss * (1.0f / 256.0f) - mu * mu + 1e-5f);
            float4 pa, pb;
            pa.x = f2tf((xa.x - mu) * rstd * w0.x + b0.x);
            pa.y = f2tf((xa.y - mu) * rstd * w0.y + b0.y);
            pa.z = f2tf((xa.z - mu) * rstd * w0.z + b0.z);
            pa.w = f2tf((xa.w - mu) * rstd * w0.w + b0.w);
            pb.x = f2tf((xb.x - mu) * rstd * w1.x + b1.x);
            pb.y = f2tf((xb.y - mu) * rstd * w1.y + b1.y);
            pb.z = f2tf((xb.z - mu) * rstd * w1.z + b1.z);
            pb.w = f2tf((xb.w - mu) * rstd * w1.w + b1.w);
            const int srw = (r & 7) << 2;
            *(float4*)(sxn + r * 256 + ((lane * 4) ^ srw))       = pa;
            *(float4*)(sxn + r * 256 + 128 + ((lane * 4) ^ srw)) = pb;
        }
    }

    float acc[12][4];
    #pragma unroll
    for (int n = 0; n < 12; ++n)
        #pragma unroll
        for (int e = 0; e < 4; ++e) acc[n][e] = 0.0f;

    const int w16 = wid * 16;
    const float* const xrow = sxn + (w16 + g) * 256;
    const int sw = g << 2;
    const float scale = 0.17677669529663689f;        // 32^-0.5
    float bias[8];

    #pragma unroll 1
    for (int cid = 0; cid < 32; ++cid) {
        const int h = cid >> 2, q = cid & 3;
        if (cid == 31) { CP_WAIT(0); } else { CP_WAIT(1); }
        __syncthreads();                              // chunk cid ready
        if (cid + 2 < 32) stage(cid + 2);

        if (q == 0) {
            #pragma unroll
            for (int j = 0; j < 8; ++j) {
                int ridx = (g >= 1 && j >= 1) ? (g - j + 6) : 13;
                bias[j] = __ldg(relt + ridx * 8 + h);
            }
        }

        // ---- GEMM1 on chunk: K=64, warp tile m16 x n96 ----
        const float2* const bw2 = (const float2*)(srng + (cid % 3) * 6144);
        const int qo = q * 64;
        #pragma unroll
        for (int ks = 0; ks < 8; ++ks) {
            const int o1 = (ks * 8 + t) ^ sw;
            const int o2 = (ks * 8 + t + 4) ^ sw;
            float4 fa;
            fa.x = xrow[qo + o1];
            fa.y = xrow[qo + o1 + 2048];
            fa.z = xrow[qo + o2];
            fa.w = xrow[qo + o2 + 2048];
            #pragma unroll
            for (int nt = 0; nt < 12; ++nt) {
                const float2 fb = bw2[(ks * 12 + nt) * 32 + lane];
                mma8(acc[nt], fa, fb);
            }
        }

        if (q == 3) {
            // ---- attention for head h (purely intra-warp) ----
            __syncthreads();                          // ring slot reads done -> reuse as bounce
            float* const a2buf = srng + (cid % 3) * 6144;   // 16KB needed, 24KB slot
            #pragma unroll
            for (int bb = 0; bb < 2; ++bb) {          // rows g (bb=0) / g+8 (bb=1)
                float qv[8], kv[8], vv[8];
                #pragma unroll
                for (int n = 0; n < 4; ++n) {
                    qv[2*n] = acc[n][2*bb];     qv[2*n+1] = acc[n][2*bb+1];
                    kv[2*n] = acc[4+n][2*bb];   kv[2*n+1] = acc[4+n][2*bb+1];
                    vv[2*n] = acc[8+n][2*bb];   vv[2*n+1] = acc[8+n][2*bb+1];
                }
                float simv[8];
                #pragma unroll
                for (int j = 0; j < 8; ++j) {
                    float p = 0.0f;
                    #pragma unroll
                    for (int r = 0; r < 8; ++r)
                        p = fmaf(qv[r], __shfl_sync(FULLM, kv[r], (j << 2) | t), p);
                    p += __shfl_xor_sync(FULLM, p, 1);
                    p += __shfl_xor_sync(FULLM, p, 2);
                    simv[j] = p * scale + bias[j];
                }
                float mx = simv[0];
                #pragma unroll
                for (int j = 1; j < 8; ++j) mx = fmaxf(mx, simv[j]);
                float ssum = 0.0f;
                #pragma unroll
                for (int j = 0; j < 8; ++j) { simv[j] = __expf(simv[j] - mx); ssum += simv[j]; }
                const float inv = 1.0f / ssum;
                float ov[8];
                #pragma unroll
                for (int r = 0; r < 8; ++r) ov[r] = 0.0f;
                #pragma unroll
                for (int j = 0; j < 8; ++j) {
                    const float aj = simv[j] * inv;
                    #pragma unroll
                    for (int r = 0; r < 8; ++r)
                        ov[r] = fmaf(aj, __shfl_sync(FULLM, vv[r], (j << 2) | t), ov[r]);
                }
                // bounce row R, cols d ^ (g<<2)   (same swizzle family as xn)
                const int R = w16 + bb * 8 + g;
                float* dstb = a2buf + R * 32;
                #pragma unroll
                for (int n = 0; n < 4; ++n) {
                    float2 p2;
                    p2.x = f2tf(ov[2*n]);
                    p2.y = f2tf(ov[2*n+1]);
                    *(float2*)(dstb + ((n * 8 + 2 * t) ^ sw)) = p2;
                }
            }
            #pragma unroll
            for (int n = 0; n < 12; ++n)
                #pragma unroll
                for (int e = 0; e < 4; ++e) acc[n][e] = 0.0f;
            __syncthreads();                          // bounce complete
            // coalesced copy: bounce (4096 floats) -> g_a2 head block
            float* dst = g_a2 + (size_t)cta * 32768 + h * 4096;
            #pragma unroll
            for (int i = 0; i < 4; ++i) {
                const int fi = (tid + i * 256) * 4;
                *(float4*)(dst + fi) = *(const float4*)(a2buf + fi);
            }
        }
    }
}

// ============================================================
// K2: out = A2 @ w_out.  512 threads, warp = m32 x n64.
// 8 K-chunks of 32 (one head each), ring-3.
// smem: ring 3 x (A 16KB + B 32KB) = 144KB; epilogue reuses for transpose
// ============================================================
#define K2_SLOT  12288
#define K2_SMEM  (3 * K2_SLOT * 4)

__global__ void __launch_bounds__(512, 1) attn_k2(float* __restrict__ out)
{
    extern __shared__ __align__(16) float sm[];
    const int tid  = threadIdx.x;
    const int wid  = tid >> 5;
    const int lane = tid & 31;
    const int g = lane >> 2, t = lane & 3;
    const int mgrp = wid & 3, ngrp = wid >> 2;       // 4 m-groups x 4 n-groups
    const int cta = blockIdx.x;
    const uint32_t sm_u = smem_u32(sm);

    auto stage = [&](int q) {
        const uint32_t dstb = sm_u + (uint32_t)(q % 3) * (K2_SLOT * 4u);
        const float* asrc = g_a2 + (size_t)cta * 32768 + q * 4096;
        #pragma unroll
        for (int i = 0; i < 2; ++i)
            CP16(dstb + (uint32_t)(tid + i * 512) * 16u, asrc + (tid + i * 512) * 4);
        const float* bsrc = g_w2t + q * 8192;
        #pragma unroll
        for (int i = 0; i < 4; ++i)
            CP16(dstb + 16384u + (uint32_t)(tid + i * 512) * 16u, bsrc + (tid + i * 512) * 4);
        CP_COMMIT();
    };
    stage(0);
    stage(1);

    float acc[8][2][4];
    #pragma unroll
    for (int n = 0; n < 8; ++n)
        #pragma unroll
        for (int m = 0; m < 2; ++m)
            #pragma unroll
            for (int e = 0; e < 4; ++e) acc[n][m][e] = 0.0f;

    const int sw = g << 2;
    #pragma unroll 1
    for (int q = 0; q < 8; ++q) {
        if (q == 7) { CP_WAIT(0); } else { CP_WAIT(1); }
        __syncthreads();
        if (q + 2 < 8) stage(q + 2);
        const float* const sA = sm + (q % 3) * K2_SLOT;          // [128][32] swizzled
        const float2* const bb2 = (const float2*)(sA + 4096);    // fragment order
        #pragma unroll
        for (int ksl = 0; ksl < 4; ++ksl) {
            const int o1 = (ksl * 8 + t) ^ sw;
            const int o2 = (ksl * 8 + t + 4) ^ sw;
            float4 fa[2];
            #pragma unroll
            for (int m = 0; m < 2; ++m) {
                const int r0 = (mgrp * 2 + m) * 16 + g;
                fa[m].x = sA[r0 * 32 + o1];
                fa[m].y = sA[r0 * 32 + 256 + o1];    // row +8
                fa[m].z = sA[r0 * 32 + o2];
                fa[m].w = sA[r0 * 32 + 256 + o2];
            }
            #pragma unroll
            for (int ntl = 0; ntl < 8; ++ntl) {
                const float2 fb = bb2[(ksl * 32 + ngrp * 8 + ntl) * 32 + lane];
                mma8(acc[ntl][0], fa[0], fb);
                mma8(acc[ntl][1], fa[1], fb);
            }
        }
    }

    // epilogue: regs -> padded smem -> coalesced STG.128
    __syncthreads();
    #pragma unroll
    for (int ntl = 0; ntl < 8; ++ntl) {
        #pragma unroll
        for (int m = 0; m < 2; ++m) {
            const int row0 = (mgrp * 2 + m) * 16 + g;
            const int col  = (ngrp * 8 + ntl) * 8 + 2 * t;
            *(float2*)&sm[row0 * 260 + col]       = make_float2(acc[ntl][m][0], acc[ntl][m][1]);
            *(float2*)&sm[(row0 + 8) * 260 + col] = make_float2(acc[ntl][m][2], acc[ntl][m][3]);
        }
    }
    __syncthreads();
    float* const od = out + (size_t)cta * 32768;
    #pragma unroll
    for (int i = 0; i < 16; ++i) {
        const int idx = tid + i * 512;
        const int r = idx >> 6, c4 = idx & 63;
        *(float4*)(od + r * 256 + c4 * 4) = *(const float4*)&sm[r * 260 + c4 * 4];
    }
}

extern "C" void kernel_launch(void* const* d_in, const int* in_sizes, int n_in,
                              void* d_out, int out_size) {
    const float* x    = (const float*)d_in[0];
    const float* lnw  = (const float*)d_in[1];
    const float* lnb  = (const float*)d_in[2];
    const float* wqkv = (const float*)d_in[3];
    const float* wout = (const float*)d_in[4];
    const float* relt = (const float*)d_in[5];
    // d_in[6] (rel_pos_indices) recomputed analytically in-kernel.

    prep_w1<<<768, 256>>>(wqkv);
    prep_w2<<<256, 256>>>(wout);

    cudaFuncSetAttribute(attn_k1, cudaFuncAttributeMaxDynamicSharedMemorySize, K1_SMEM);
    cudaFuncSetAttribute(attn_k2, cudaFuncAttributeMaxDynamicSharedMemorySize, K2_SMEM);
    attn_k1<<<2048, 256, K1_SMEM>>>(x, lnw, lnb, relt);
    attn_k2<<<2048, 512, K2_SMEM>>>((float*)d_out);
}

// round 8
// speedup vs baseline: 1.8284x; 1.7638x over previous
#include <cuda_runtime.h>
#include <cuda_fp16.h>
#include <cstdint>

// ============================================================
// Attention1D: LN -> QKV GEMM -> 8-head window attention -> out GEMM
// fp16 mma.sync m16n8k16 (same 10-bit mantissa as tf32, 2x FLOP/inst,
// half the operand bytes). tcgen05 unavailable (harness PTX = compute_103).
// A2 is written by K1 in K2's exact A-fragment order.
// ============================================================

#define FULLM 0xffffffffu

// B1 frags: [cid(32)=h*4+q][ks(4)][nt(12)][lane(32)][b01(2)] half2  (384KB)
__device__ __align__(16) __half2 g_w1t[98304];
// B2 frags: [q(8)][ks2(2)][nt(32)][lane(32)][b01(2)] half2          (128KB)
__device__ __align__(16) __half2 g_w2t[32768];
// A2 frags: [cta(2048)][h(8)][hi2(2)][mt(8)][lane(32)][a0..a3] halves (128MB)
__device__ __align__(16) __half g_a2[67108864];

static __device__ __forceinline__ void mma16(float* c, uint32_t a0, uint32_t a1,
                                             uint32_t a2, uint32_t a3,
                                             uint32_t b0, uint32_t b1) {
    asm volatile(
        "mma.sync.aligned.m16n8k16.row.col.f32.f16.f16.f32 "
        "{%0,%1,%2,%3}, {%4,%5,%6,%7}, {%8,%9}, {%0,%1,%2,%3};"
        : "+f"(c[0]), "+f"(c[1]), "+f"(c[2]), "+f"(c[3])
        : "r"(a0), "r"(a1), "r"(a2), "r"(a3), "r"(b0), "r"(b1));
}
static __device__ __forceinline__ uint32_t h2u(float a, float b) {
    __half2 h = __floats2half2_rn(a, b);
    return *(uint32_t*)&h;
}
static __device__ __forceinline__ uint32_t smem_u32(const void* p) {
    uint32_t a;
    asm("{ .reg .u64 t; cvta.to.shared.u64 t, %1; cvt.u32.u64 %0, t; }" : "=r"(a) : "l"(p));
    return a;
}
#define CP16(dst, src) \
    asm volatile("cp.async.ca.shared.global [%0], [%1], 16;" :: "r"(dst), "l"(src))
#define CP_COMMIT() asm volatile("cp.async.commit_group;" ::: "memory")
#define CP_WAIT(n)  asm volatile("cp.async.wait_group %0;" :: "n"(n) : "memory")

// ---------------- weight prep (fp16 round + fragment-order transpose) ----------------
__global__ void prep_w1(const float* __restrict__ wqkv) {
    int p = blockIdx.x * 256 + threadIdx.x;          // < 98304 half2
    int b01  = p & 1;
    int lane = (p >> 1) & 31;
    int rest = p >> 6;
    int nt = rest % 12;
    int r2 = rest / 12;                              // 0..127
    int ks = r2 & 3;
    int cid = r2 >> 2;                               // 0..31
    int h = cid >> 2, q = cid & 3;
    int t = lane & 3, g = lane >> 2;
    int k0 = q * 64 + ks * 16 + b01 * 8 + 2 * t;     // K index
    int col = (nt >> 2) * 256 + h * 32 + (nt & 3) * 8 + g;  // qkv column
    g_w1t[p] = __floats2half2_rn(wqkv[k0 * 768 + col], wqkv[(k0 + 1) * 768 + col]);
}
__global__ void prep_w2(const float* __restrict__ wout) {
    int p = blockIdx.x * 256 + threadIdx.x;          // < 32768 half2
    int b01  = p & 1;
    int lane = (p >> 1) & 31;
    int nt  = (p >> 6) & 31;
    int ks2 = (p >> 11) & 1;
    int q   = p >> 12;
    int t = lane & 3, g = lane >> 2;
    int k0 = q * 32 + ks2 * 16 + b01 * 8 + 2 * t;
    int n  = nt * 8 + g;
    g_w2t[p] = __floats2half2_rn(wout[k0 * 256 + n], wout[(k0 + 1) * 256 + n]);
}

// ============================================================
// K1: LN + QKV GEMM + attention -> g_a2 (fp16, K2-fragment order)
// 8 warps, warp = m16 (rows wid*16..+15) x n96 (q|k|v of head h).
// smem: xn 64KB (row-major halves, xor-swizzled) + B1 ring 3x12KB = 100KB
// -> 2 CTAs/SM.
// ============================================================
#define K1_SMEM (65536 + 3 * 12288)

__global__ void __launch_bounds__(256, 2) attn_k1(
    const float* __restrict__ x, const float* __restrict__ lnw,
    const float* __restrict__ lnb, const float* __restrict__ relt)
{
    extern __shared__ __align__(16) char smem[];
    __half* const sxn = (__half*)smem;                // 32768 halves
    char*   const srng = smem + 65536;                // 3 x 12288 B
    const int tid  = threadIdx.x;
    const int wid  = tid >> 5;
    const int lane = tid & 31;
    const int g = lane >> 2, t = lane & 3;
    const int cta = blockIdx.x;
    const uint32_t srng_u = smem_u32(srng);

    // stage chunk cid (12KB, linear) into ring slot cid%3
    auto stage = [&](int cid2) {
        uint32_t dst = srng_u + (uint32_t)(cid2 % 3) * 12288u + (uint32_t)tid * 16u;
        const char* src = (const char*)g_w1t + cid2 * 12288 + tid * 16;
        #pragma unroll
        for (int i = 0; i < 3; ++i) CP16(dst + i * 4096u, src + i * 4096);
        CP_COMMIT();
    };
    stage(0);
    stage(1);

    // ---- LayerNorm -> xor-swizzled row-major fp16 xn (overlaps cp.async) ----
    {
        const float* xr = x + (size_t)cta * 128 * 256;
        const float4 w0 = *(const float4*)(lnw + lane * 4);
        const float4 w1 = *(const float4*)(lnw + 128 + lane * 4);
        const float4 b0 = *(const float4*)(lnb + lane * 4);
        const float4 b1 = *(const float4*)(lnb + 128 + lane * 4);
        #pragma unroll 2
        for (int rr = 0; rr < 16; ++rr) {
            const int r = wid * 16 + rr;
            const float4 xa = *(const float4*)(xr + r * 256 + lane * 4);
            const float4 xb = *(const float4*)(xr + r * 256 + 128 + lane * 4);
            float s  = xa.x + xa.y + xa.z + xa.w + xb.x + xb.y + xb.z + xb.w;
            float ss = xa.x*xa.x + xa.y*xa.y + xa.z*xa.z + xa.w*xa.w
                     + xb.x*xb.x + xb.y*xb.y + xb.z*xb.z + xb.w*xb.w;
            #pragma unroll
            for (int o2 = 16; o2; o2 >>= 1) {
                s  += __shfl_xor_sync(FULLM, s,  o2);
                ss += __shfl_xor_sync(FULLM, ss, o2);
            }
            const float mu   = s * (1.0f / 256.0f);
            const float rstd = rsqrtf(ss * (1.0f / 256.0f) - mu * mu + 1e-5f);
            const int srw = (r & 7) << 3;             // half-index XOR swizzle
            uint2 pa, pb;
            pa.x = h2u((xa.x - mu) * rstd * w0.x + b0.x, (xa.y - mu) * rstd * w0.y + b0.y);
            pa.y = h2u((xa.z - mu) * rstd * w0.z + b0.z, (xa.w - mu) * rstd * w0.w + b0.w);
            pb.x = h2u((xb.x - mu) * rstd * w1.x + b1.x, (xb.y - mu) * rstd * w1.y + b1.y);
            pb.y = h2u((xb.z - mu) * rstd * w1.z + b1.z, (xb.w - mu) * rstd * w1.w + b1.w);
            *(uint2*)(sxn + r * 256 + ((lane * 4) ^ srw))         = pa;
            *(uint2*)(sxn + r * 256 + ((128 + lane * 4) ^ srw))   = pb;
        }
    }

    float acc[12][4];
    #pragma unroll
    for (int n = 0; n < 12; ++n)
        #pragma unroll
        for (int e = 0; e < 4; ++e) acc[n][e] = 0.0f;

    const int w16 = wid * 16;
    const __half* const xrow0 = sxn + (w16 + g) * 256;      // row g
    const __half* const xrow1 = xrow0 + 8 * 256;            // row g+8
    const int sx = g << 3;
    const float scale = 0.17677669529663689f;               // 32^-0.5
    float bias[8];

    #pragma unroll 1
    for (int cid = 0; cid < 32; ++cid) {
        const int h = cid >> 2, q = cid & 3;
        if (cid == 31) { CP_WAIT(0); } else { CP_WAIT(1); }
        __syncthreads();                              // chunk cid ready
        if (cid + 2 < 32) stage(cid + 2);

        if (q == 0) {
            #pragma unroll
            for (int j = 0; j < 8; ++j) {
                int ridx = (g >= 1 && j >= 1) ? (g - j + 6) : 13;
                bias[j] = __ldg(relt + ridx * 8 + h);
            }
        }

        // ---- GEMM1 on chunk: K=64 (4 k16-steps), warp tile m16 x n96 ----
        const uint2* const bw2 = (const uint2*)(srng + (cid % 3) * 12288);
        #pragma unroll
        for (int ks = 0; ks < 4; ++ks) {
            const int c0 = q * 64 + ks * 16 + 2 * t;
            const uint32_t a0 = *(const uint32_t*)(xrow0 + (c0 ^ sx));
            const uint32_t a1 = *(const uint32_t*)(xrow1 + (c0 ^ sx));
            const uint32_t a2 = *(const uint32_t*)(xrow0 + ((c0 + 8) ^ sx));
            const uint32_t a3 = *(const uint32_t*)(xrow1 + ((c0 + 8) ^ sx));
            #pragma unroll
            for (int nt = 0; nt < 12; ++nt) {
                const uint2 fb = bw2[(ks * 12 + nt) * 32 + lane];
                mma16(acc[nt], a0, a1, a2, a3, fb.x, fb.y);
            }
        }

        if (q == 3) {
            // ---- attention for head h (purely intra-warp) ----
            __syncthreads();                          // ring slot reads done -> reuse
            uint4* const a2b4 = (uint4*)(srng + (cid % 3) * 12288);  // 8KB of 12KB slot
            float ov[2][8];
            #pragma unroll
            for (int bb = 0; bb < 2; ++bb) {          // rows g (bb=0) / g+8 (bb=1)
                float qv[8], kv[8], vv[8];
                #pragma unroll
                for (int n = 0; n < 4; ++n) {
                    qv[2*n] = acc[n][2*bb];     qv[2*n+1] = acc[n][2*bb+1];
                    kv[2*n] = acc[4+n][2*bb];   kv[2*n+1] = acc[4+n][2*bb+1];
                    vv[2*n] = acc[8+n][2*bb];   vv[2*n+1] = acc[8+n][2*bb+1];
                }
                float simv[8];
                #pragma unroll
                for (int j = 0; j < 8; ++j) {
                    float p = 0.0f;
                    #pragma unroll
                    for (int r = 0; r < 8; ++r)
                        p = fmaf(qv[r], __shfl_sync(FULLM, kv[r], (j << 2) | t), p);
                    p += __shfl_xor_sync(FULLM, p, 1);
                    p += __shfl_xor_sync(FULLM, p, 2);
                    simv[j] = p * scale + bias[j];
                }
                float mx = simv[0];
                #pragma unroll
                for (int j = 1; j < 8; ++j) mx = fmaxf(mx, simv[j]);
                float ssum = 0.0f;
                #pragma unroll
                for (int j = 0; j < 8; ++j) { simv[j] = __expf(simv[j] - mx); ssum += simv[j]; }
                const float inv = 1.0f / ssum;
                #pragma unroll
                for (int r = 0; r < 8; ++r) ov[bb][r] = 0.0f;
                #pragma unroll
                for (int j = 0; j < 8; ++j) {
                    const float aj = simv[j] * inv;
                    #pragma unroll
                    for (int r = 0; r < 8; ++r)
                        ov[bb][r] = fmaf(aj, __shfl_sync(FULLM, vv[r], (j << 2) | t), ov[bb][r]);
                }
            }
            #pragma unroll
            for (int n = 0; n < 12; ++n)
                #pragma unroll
                for (int e = 0; e < 4; ++e) acc[n][e] = 0.0f;
            // write K2-fragment-order fp16: [hi2][mt=wid][lane]{a0,a1,a2,a3}
            #pragma unroll
            for (int hi2 = 0; hi2 < 2; ++hi2) {
                uint4 w;
                w.x = h2u(ov[0][4*hi2 + 0], ov[0][4*hi2 + 1]);   // a0: row g,  k 2t,2t+1
                w.y = h2u(ov[1][4*hi2 + 0], ov[1][4*hi2 + 1]);   // a1: row g+8
                w.z = h2u(ov[0][4*hi2 + 2], ov[0][4*hi2 + 3]);   // a2: row g,  k 2t+8,+9
                w.w = h2u(ov[1][4*hi2 + 2], ov[1][4*hi2 + 3]);   // a3: row g+8
                a2b4[(hi2 * 8 + wid) * 32 + lane] = w;
            }
            __syncthreads();                          // bounce complete
            // coalesced copy: bounce (8KB) -> g_a2 head block
            uint4* dst = (uint4*)(g_a2 + (size_t)cta * 32768 + h * 4096);
            #pragma unroll
            for (int i = 0; i < 2; ++i)
                dst[tid + i * 256] = a2b4[tid + i * 256];
        }
    }
}

// ============================================================
// K2: out = A2 @ w_out.  512 threads, warp = m32 x n64 (4x4 groups).
// 8 K-chunks of 32 (one head each), ring-3. A frags via single LDS.128.
// smem: ring 3x24KB = 72KB; epilogue reuses 133KB for fp32 transpose.
// ============================================================
#define K2_SMEM 133120

__global__ void __launch_bounds__(512, 1) attn_k2(float* __restrict__ out)
{
    extern __shared__ __align__(16) char smem[];
    const int tid  = threadIdx.x;
    const int wid  = tid >> 5;
    const int lane = tid & 31;
    const int g = lane >> 2, t = lane & 3;
    const int mgrp = wid & 3, ngrp = wid >> 2;       // 4 m-groups x 4 n-groups
    const int cta = blockIdx.x;
    const uint32_t sm_u = smem_u32(smem);

    auto stage = [&](int q) {
        const uint32_t dstb = sm_u + (uint32_t)(q % 3) * 24576u;
        const char* asrc = (const char*)(g_a2 + (size_t)cta * 32768 + q * 4096);
        CP16(dstb + (uint32_t)tid * 16u, asrc + tid * 16);             // A 8KB
        const char* bsrc = (const char*)g_w2t + q * 16384;
        #pragma unroll
        for (int i = 0; i < 2; ++i)                                     // B 16KB
            CP16(dstb + 8192u + (uint32_t)(tid + i * 512) * 16u, bsrc + (tid + i * 512) * 16);
        CP_COMMIT();
    };
    stage(0);
    stage(1);

    float acc[8][2][4];
    #pragma unroll
    for (int n = 0; n < 8; ++n)
        #pragma unroll
        for (int m = 0; m < 2; ++m)
            #pragma unroll
            for (int e = 0; e < 4; ++e) acc[n][m][e] = 0.0f;

    #pragma unroll 1
    for (int q = 0; q < 8; ++q) {
        if (q == 7) { CP_WAIT(0); } else { CP_WAIT(1); }
        __syncthreads();
        if (q + 2 < 8) stage(q + 2);
        const uint4* const a4 = (const uint4*)(smem + (q % 3) * 24576);
        const uint2* const b2 = (const uint2*)(smem + (q % 3) * 24576 + 8192);
        #pragma unroll
        for (int ks2 = 0; ks2 < 2; ++ks2) {
            uint4 fa[2];
            #pragma unroll
            for (int m = 0; m < 2; ++m)
                fa[m] = a4[(ks2 * 8 + mgrp * 2 + m) * 32 + lane];
            #pragma unroll
            for (int ntl = 0; ntl < 8; ++ntl) {
                const uint2 fb = b2[(ks2 * 32 + ngrp * 8 + ntl) * 32 + lane];
                mma16(acc[ntl][0], fa[0].x, fa[0].y, fa[0].z, fa[0].w, fb.x, fb.y);
                mma16(acc[ntl][1], fa[1].x, fa[1].y, fa[1].z, fa[1].w, fb.x, fb.y);
            }
        }
    }

    // epilogue: regs -> padded smem -> coalesced STG.128
    __syncthreads();
    float* const smf = (float*)smem;
    #pragma unroll
    for (int ntl = 0; ntl < 8; ++ntl) {
        #pragma unroll
        for (int m = 0; m < 2; ++m) {
            const int row0 = (mgrp * 2 + m) * 16 + g;
            const int col  = (ngrp * 8 + ntl) * 8 + 2 * t;
            *(float2*)&smf[row0 * 260 + col]       = make_float2(acc[ntl][m][0], acc[ntl][m][1]);
            *(float2*)&smf[(row0 + 8) * 260 + col] = make_float2(acc[ntl][m][2], acc[ntl][m][3]);
        }
    }
    __syncthreads();
    float* const od = out + (size_t)cta * 32768;
    #pragma unroll
    for (int i = 0; i < 16; ++i) {
        const int idx = tid + i * 512;
        const int r = idx >> 6, c4 = idx & 63;
        *(float4*)(od + r * 256 + c4 * 4) = *(const float4*)&smf[r * 260 + c4 * 4];
    }
}

extern "C" void kernel_launch(void* const* d_in, const int* in_sizes, int n_in,
                              void* d_out, int out_size) {
    const float* x    = (const float*)d_in[0];
    const float* lnw  = (const float*)d_in[1];
    const float* lnb  = (const float*)d_in[2];
    const float* wqkv = (const float*)d_in[3];
    const float* wout = (const float*)d_in[4];
    const float* relt = (const float*)d_in[5];
    // d_in[6] (rel_pos_indices) recomputed analytically in-kernel.

    prep_w1<<<384, 256>>>(wqkv);
    prep_w2<<<128, 256>>>(wout);

    cudaFuncSetAttribute(attn_k1, cudaFuncAttributeMaxDynamicSharedMemorySize, K1_SMEM);
    cudaFuncSetAttribute(attn_k2, cudaFuncAttributeMaxDynamicSharedMemorySize, K2_SMEM);
    attn_k1<<<2048, 256, K1_SMEM>>>(x, lnw, lnb, relt);
    attn_k2<<<2048, 512, K2_SMEM>>>((float*)d_out);
}